// round 15
// baseline (speedup 1.0000x reference)
#include <cuda_runtime.h>
#include <cuda_bf16.h>
#include <cuda_fp16.h>
#include <cstdint>

#define NN 100000
#define EE 1600000
#define DD 128
#define SCAN_CHUNK 1024
#define SCAN_B ((NN + SCAN_CHUNK - 1) / SCAN_CHUNK)   // 98

// ---------------- static device scratch (no allocations allowed) ----------------
__device__ int    g_outdeg[NN];
__device__ int    g_indeg[NN];
__device__ float  g_nsrc[NN];
__device__ float  g_ndst[NN];
__device__ int    g_off[NN + 1];
__device__ int    g_cur[NN];
__device__ int    g_part[SCAN_B + 1];
__device__ int    g_esrc[EE];
__device__ __half g_F16[(size_t)NN * DD];  // features converted to fp16 (once)
__device__ __half g_G[(size_t)NN * DD];    // GEMM output (gather source)
__device__ __half g_h1[(size_t)NN * DD];   // layer-1 activations (ns-scaled)
__device__ __half g_W1t[DD * DD];          // W1 fp16, transposed [N,K]
__device__ __half g_W2t[DD * DD];          // W2 fp16, transposed [N,K]

__device__ __forceinline__ uint32_t smem_u32(const void* p) {
    uint32_t a;
    asm("{ .reg .u64 t; cvta.to.shared.u64 t, %1; cvt.u32.u64 %0, t; }" : "=r"(a) : "l"(p));
    return a;
}

// ---------------- streaming convert: features fp32 -> fp16 ----------------
__global__ __launch_bounds__(256)
void fconv_kernel(const float* __restrict__ f, __half* __restrict__ o, int nf4) {
    int i = blockIdx.x * blockDim.x + threadIdx.x;
    if (i < nf4) {
        float4 v = ((const float4*)f)[i];
        uint2 p;
        *(__half2*)&p.x = __floats2half2_rn(v.x, v.y);
        *(__half2*)&p.y = __floats2half2_rn(v.z, v.w);
        ((uint2*)o)[i] = p;
    }
}

// ---------------- fused setup: zero degrees + convert/transpose both W ----------------
__global__ __launch_bounds__(256)
void setup_kernel(const float* __restrict__ W1, const float* __restrict__ W2, int n) {
    int i = blockIdx.x * blockDim.x + threadIdx.x;
    if (i < n) { g_outdeg[i] = 0; g_indeg[i] = 0; }
    if (i < DD * DD) {
        int k = i >> 7, nn = i & 127;
        g_W1t[nn * DD + k] = __float2half_rn(W1[i]);
        g_W2t[nn * DD + k] = __float2half_rn(W2[i]);
    }
}

// 2 edges per thread
__global__ __launch_bounds__(256)
void count_deg_kernel(const int* __restrict__ src, const int* __restrict__ dst,
                      int E2, int E, int n) {
    int t = blockIdx.x * blockDim.x + threadIdx.x;
    if (t < E2) {
        int e = t * 2;
        if (e + 1 < E) {
            int2 s = *(const int2*)(src + e);
            int2 d = *(const int2*)(dst + e);
            if ((unsigned)s.x < (unsigned)n) atomicAdd(&g_outdeg[s.x], 1);
            if ((unsigned)s.y < (unsigned)n) atomicAdd(&g_outdeg[s.y], 1);
            if ((unsigned)d.x < (unsigned)n) atomicAdd(&g_indeg[d.x], 1);
            if ((unsigned)d.y < (unsigned)n) atomicAdd(&g_indeg[d.y], 1);
        } else {
            int s = src[e], d = dst[e];
            if ((unsigned)s < (unsigned)n) atomicAdd(&g_outdeg[s], 1);
            if ((unsigned)d < (unsigned)n) atomicAdd(&g_indeg[d], 1);
        }
    }
}

// norms
__global__ __launch_bounds__(256)
void norm_kernel(int n) {
    int i = blockIdx.x * blockDim.x + threadIdx.x;
    if (i < n) {
        g_nsrc[i] = rsqrtf(fmaxf((float)g_outdeg[i], 1.0f));
        g_ndst[i] = rsqrtf(fmaxf((float)g_indeg[i], 1.0f));
    }
}

// ---- scan pass 1 ----
__global__ __launch_bounds__(256)
void scan_reduce_kernel(int n) {
    __shared__ int wsum[8];
    int b = blockIdx.x;
    int tid = threadIdx.x;
    int idx = b * SCAN_CHUNK + tid * 4;
    int s = 0;
    #pragma unroll
    for (int t = 0; t < 4; t++)
        if (idx + t < n) s += g_indeg[idx + t];
    #pragma unroll
    for (int o = 16; o > 0; o >>= 1) s += __shfl_down_sync(0xffffffffu, s, o);
    int lane = tid & 31, wid = tid >> 5;
    if (lane == 0) wsum[wid] = s;
    __syncthreads();
    if (tid == 0) {
        int t = 0;
        #pragma unroll
        for (int w = 0; w < 8; w++) t += wsum[w];
        g_part[b] = t;
    }
}

__global__ __launch_bounds__(128)
void scan_partials_kernel(int B, int E) {
    __shared__ int sdata[128];
    int tid = threadIdx.x;
    int v = (tid < B) ? g_part[tid] : 0;
    sdata[tid] = v;
    __syncthreads();
    #pragma unroll
    for (int o = 1; o < 128; o <<= 1) {
        int t = (tid >= o) ? sdata[tid - o] : 0;
        __syncthreads();
        sdata[tid] += t;
        __syncthreads();
    }
    if (tid < B) g_part[tid] = sdata[tid] - v;
    if (tid == 0) g_off[NN] = E;
}

__global__ __launch_bounds__(256)
void scan_down_kernel(int n) {
    __shared__ int wscan[8];
    int b = blockIdx.x;
    int tid = threadIdx.x;
    int lane = tid & 31, wid = tid >> 5;
    int idx = b * SCAN_CHUNK + tid * 4;
    int v0 = 0, v1 = 0, v2 = 0, v3 = 0;
    if (idx + 0 < n) v0 = g_indeg[idx + 0];
    if (idx + 1 < n) v1 = g_indeg[idx + 1];
    if (idx + 2 < n) v2 = g_indeg[idx + 2];
    if (idx + 3 < n) v3 = g_indeg[idx + 3];
    int tsum = v0 + v1 + v2 + v3;
    int x = tsum;
    #pragma unroll
    for (int o = 1; o < 32; o <<= 1) {
        int y = __shfl_up_sync(0xffffffffu, x, o);
        if (lane >= o) x += y;
    }
    if (lane == 31) wscan[wid] = x;
    __syncthreads();
    if (wid == 0 && lane < 8) {
        int s = wscan[lane];
        #pragma unroll
        for (int o = 1; o < 8; o <<= 1) {
            int y = __shfl_up_sync(0x000000ffu, s, o);
            if (lane >= o) s += y;
        }
        wscan[lane] = s;
    }
    __syncthreads();
    int base = g_part[b] + (wid ? wscan[wid - 1] : 0) + (x - tsum);
    if (idx + 0 < n) { g_off[idx + 0] = base;            g_cur[idx + 0] = base; }
    if (idx + 1 < n) { g_off[idx + 1] = base + v0;       g_cur[idx + 1] = base + v0; }
    if (idx + 2 < n) { int t = base + v0 + v1;      g_off[idx + 2] = t; g_cur[idx + 2] = t; }
    if (idx + 3 < n) { int t = base + v0 + v1 + v2; g_off[idx + 3] = t; g_cur[idx + 3] = t; }
}

// 2 edges per thread
__global__ __launch_bounds__(256)
void fill_csr_kernel(const int* __restrict__ src, const int* __restrict__ dst,
                     int E2, int E, int n) {
    int t = blockIdx.x * blockDim.x + threadIdx.x;
    if (t < E2) {
        int e = t * 2;
        if (e + 1 < E) {
            int2 s = *(const int2*)(src + e);
            int2 d = *(const int2*)(dst + e);
            if ((unsigned)s.x < (unsigned)n && (unsigned)d.x < (unsigned)n)
                g_esrc[atomicAdd(&g_cur[d.x], 1)] = s.x;
            if ((unsigned)s.y < (unsigned)n && (unsigned)d.y < (unsigned)n)
                g_esrc[atomicAdd(&g_cur[d.y], 1)] = s.y;
        } else {
            int s = src[e], d = dst[e];
            if ((unsigned)s < (unsigned)n && (unsigned)d < (unsigned)n)
                g_esrc[atomicAdd(&g_cur[d], 1)] = s;
        }
    }
}

// ---------------- pull-based SpMM (fp16 gather) + fused nd/bias/relu (+optional ns) ----------------
template <typename TOut, int NSCALE>
__global__ __launch_bounds__(256)
void spmm_kernel(const __half* __restrict__ G, const float* __restrict__ bias,
                 TOut* __restrict__ out, int n) {
    int gw = (blockIdx.x * blockDim.x + threadIdx.x) >> 5;
    if (gw >= n) return;
    int lane = threadIdx.x & 31;
    int beg = g_off[gw];
    int end = g_off[gw + 1];
    const uint2* hp = (const uint2*)G;
    float4 acc = make_float4(0.f, 0.f, 0.f, 0.f);
    int e = beg;
    for (; e + 3 < end; e += 4) {
        int u0 = g_esrc[e], u1 = g_esrc[e + 1], u2 = g_esrc[e + 2], u3 = g_esrc[e + 3];
        uint2 a = hp[(size_t)u0 * 32 + lane];
        uint2 b = hp[(size_t)u1 * 32 + lane];
        uint2 c = hp[(size_t)u2 * 32 + lane];
        uint2 d = hp[(size_t)u3 * 32 + lane];
        float2 f;
        f = __half22float2(*(__half2*)&a.x); acc.x += f.x; acc.y += f.y;
        f = __half22float2(*(__half2*)&a.y); acc.z += f.x; acc.w += f.y;
        f = __half22float2(*(__half2*)&b.x); acc.x += f.x; acc.y += f.y;
        f = __half22float2(*(__half2*)&b.y); acc.z += f.x; acc.w += f.y;
        f = __half22float2(*(__half2*)&c.x); acc.x += f.x; acc.y += f.y;
        f = __half22float2(*(__half2*)&c.y); acc.z += f.x; acc.w += f.y;
        f = __half22float2(*(__half2*)&d.x); acc.x += f.x; acc.y += f.y;
        f = __half22float2(*(__half2*)&d.y); acc.z += f.x; acc.w += f.y;
    }
    for (; e < end; e++) {
        uint2 a = hp[(size_t)g_esrc[e] * 32 + lane];
        float2 f;
        f = __half22float2(*(__half2*)&a.x); acc.x += f.x; acc.y += f.y;
        f = __half22float2(*(__half2*)&a.y); acc.z += f.x; acc.w += f.y;
    }
    float nd = g_ndst[gw];
    float4 b4 = ((const float4*)bias)[lane];
    float4 o;
    o.x = fmaxf(acc.x * nd + b4.x, 0.f);
    o.y = fmaxf(acc.y * nd + b4.y, 0.f);
    o.z = fmaxf(acc.z * nd + b4.z, 0.f);
    o.w = fmaxf(acc.w * nd + b4.w, 0.f);
    if constexpr (NSCALE) {
        float ns = g_nsrc[gw];   // fold next layer's src-norm into stored activation
        o.x *= ns; o.y *= ns; o.z *= ns; o.w *= ns;
    }
    if constexpr (sizeof(TOut) == 4) {
        ((float4*)out)[(size_t)gw * 32 + lane] = o;
    } else {
        uint2 p;
        *(__half2*)&p.x = __floats2half2_rn(o.x, o.y);
        *(__half2*)&p.y = __floats2half2_rn(o.z, o.w);
        ((uint2*)out)[(size_t)gw * 32 + lane] = p;
    }
}

// ---------------- HMMA GEMM (fp16 A): C = [ns ⊙] (A @ W), fp16 out ----------------
// 2x4 warp tiling: warp = 64 M-rows x 32 N-cols. smem 69.6KB -> 3 CTAs/SM. Coalesced loads.
#define GP 272
#define TROWS 128
#define SM_A   0
#define SM_W   (TROWS * GP)
#define GEMM_SMEM ((TROWS + 128) * GP)   // 69632

__device__ __forceinline__ void ldsm_x4(uint32_t* r, uint32_t addr) {
    asm volatile("ldmatrix.sync.aligned.m8n8.x4.shared.b16 {%0,%1,%2,%3}, [%4];"
                 : "=r"(r[0]), "=r"(r[1]), "=r"(r[2]), "=r"(r[3]) : "r"(addr));
}
__device__ __forceinline__ void mma_f16(float* c, const uint32_t* a, uint32_t b0, uint32_t b1) {
    asm volatile("mma.sync.aligned.m16n8k16.row.col.f32.f16.f16.f32 "
                 "{%0,%1,%2,%3}, {%4,%5,%6,%7}, {%8,%9}, {%0,%1,%2,%3};"
                 : "+f"(c[0]), "+f"(c[1]), "+f"(c[2]), "+f"(c[3])
                 : "r"(a[0]), "r"(a[1]), "r"(a[2]), "r"(a[3]), "r"(b0), "r"(b1));
}

template <int NSCALE>
__global__ __launch_bounds__(256, 3)
void gemm_tc_kernel(const __half* __restrict__ A,
                    const __half* __restrict__ W,
                    __half* __restrict__ C, int n) {
    extern __shared__ char sm[];
    uint32_t base = smem_u32(sm);
    const int tid = threadIdx.x;
    const int w = tid >> 5, lane = tid & 31;
    const int wm = w >> 2;           // 0..1 : M-warp  (64 rows)
    const int wn = w & 3;            // 0..3 : N-warp  (32 cols)
    const int row0 = blockIdx.x * TROWS;

    // W tile: 128 rows x 256B (fp16), coalesced
    for (int i = tid; i < 2048; i += 256) {
        int rr = i >> 4, q = i & 15;
        *(uint4*)(sm + SM_W + rr * GP + q * 16) = ((const uint4*)W)[i];
    }
    // A tile (fp16), fully coalesced
    {
        const uint4* ap = (const uint4*)A;     // 16 u4 per row
        #pragma unroll
        for (int i = 0; i < 8; i++) {
            int f = tid + 256 * i;              // 0..2047
            int r = f >> 4, c8 = f & 15;
            int gr = row0 + r;
            uint4 v = make_uint4(0u, 0u, 0u, 0u);
            if (gr < n) v = ap[(size_t)gr * 16 + c8];
            *(uint4*)(sm + SM_A + r * GP + c8 * 16) = v;
        }
    }
    __syncthreads();

    // acc[ab][np][4]: 4 A-blocks (16 rows) x 4 n8-blocks (8 cols)
    float acc[4][4][4];
    #pragma unroll
    for (int a = 0; a < 4; a++)
        #pragma unroll
        for (int p = 0; p < 4; p++)
            #pragma unroll
            for (int q = 0; q < 4; q++) acc[a][p][q] = 0.f;

    int i4 = lane >> 3, l7 = lane & 7;
    uint32_t aRowIn = (uint32_t)((i4 & 1) * 8 + l7);
    uint32_t aK8    = (uint32_t)((i4 >> 1) * 8);
    uint32_t aBase = base + SM_A + (wm * 64 + aRowIn) * GP + aK8 * 2;
    uint32_t wRowIn = (uint32_t)((lane & 7) + ((lane >> 4) << 3));
    uint32_t wK8    = (uint32_t)(((lane >> 3) & 1) * 8);
    uint32_t wW = base + SM_W + (wn * 32 + wRowIn) * GP + wK8 * 2;

    #pragma unroll
    for (int kk = 0; kk < 8; kk++) {
        uint32_t wh0[4], wh1[4];
        ldsm_x4(wh0, wW + kk * 32);               // j-pair 0: n8 blocks 0,1
        ldsm_x4(wh1, wW + 16 * GP + kk * 32);     // j-pair 1: n8 blocks 2,3
        #pragma unroll
        for (int ab = 0; ab < 4; ab++) {
            uint32_t ah[4];
            ldsm_x4(ah, aBase + ab * 16 * GP + kk * 32);
            mma_f16(acc[ab][0], ah, wh0[0], wh0[1]);
            mma_f16(acc[ab][1], ah, wh0[2], wh0[3]);
            mma_f16(acc[ab][2], ah, wh1[0], wh1[1]);
            mma_f16(acc[ab][3], ah, wh1[2], wh1[3]);
        }
    }

    // epilogue: optional ns row-scale, write fp16
    int c0 = (lane & 3) * 2;
    #pragma unroll
    for (int ab = 0; ab < 4; ab++) {
        int r0 = row0 + wm * 64 + ab * 16 + (lane >> 2);
        float ns0 = 1.f, ns1 = 1.f;
        if constexpr (NSCALE) {
            ns0 = (r0 < n) ? g_nsrc[r0] : 0.f;
            ns1 = (r0 + 8 < n) ? g_nsrc[r0 + 8] : 0.f;
        }
        #pragma unroll
        for (int np = 0; np < 4; np++) {
            int nn = wn * 32 + np * 8 + c0;
            if (r0 < n)
                *(__half2*)(C + (size_t)r0 * DD + nn) = __floats2half2_rn(acc[ab][np][0] * ns0, acc[ab][np][1] * ns0);
            if (r0 + 8 < n)
                *(__half2*)(C + (size_t)(r0 + 8) * DD + nn) = __floats2half2_rn(acc[ab][np][2] * ns1, acc[ab][np][3] * ns1);
        }
    }
}

// ---------------- launch ----------------
extern "C" void kernel_launch(void* const* d_in, const int* in_sizes, int n_in,
                              void* d_out, int out_size) {
    const float* features = (const float*)d_in[0];
    const int*   src      = (const int*)d_in[1];   // jnp.int64 downgrades to int32 (x64 off)
    const int*   dst      = (const int*)d_in[2];
    const float* W1       = (const float*)d_in[3];
    const float* b1       = (const float*)d_in[4];
    const float* W2       = (const float*)d_in[5];
    const float* b2       = (const float*)d_in[6];
    float*       out      = (float*)d_out;

    int n = in_sizes[0] / DD;   // 100000
    int E = in_sizes[1];        // 1600000

    __half *F16, *G, *h1, *w1t, *w2t;
    cudaGetSymbolAddress((void**)&F16, g_F16);
    cudaGetSymbolAddress((void**)&G, g_G);
    cudaGetSymbolAddress((void**)&h1, g_h1);
    cudaGetSymbolAddress((void**)&w1t, g_W1t);
    cudaGetSymbolAddress((void**)&w2t, g_W2t);

    cudaFuncSetAttribute(gemm_tc_kernel<1>,
                         cudaFuncAttributeMaxDynamicSharedMemorySize, GEMM_SMEM);
    cudaFuncSetAttribute(gemm_tc_kernel<0>,
                         cudaFuncAttributeMaxDynamicSharedMemorySize, GEMM_SMEM);

    // side stream + events (host-side objects only)
    cudaStream_t s2;
    cudaEvent_t evStart, evNorm, evConvGemm;
    cudaStreamCreateWithFlags(&s2, cudaStreamNonBlocking);
    cudaEventCreateWithFlags(&evStart, cudaEventDisableTiming);
    cudaEventCreateWithFlags(&evNorm, cudaEventDisableTiming);
    cudaEventCreateWithFlags(&evConvGemm, cudaEventDisableTiming);

    int tb = 256;
    int gN = (n + tb - 1) / tb;
    int E2 = (E + 1) / 2;
    int gE2 = (E2 + tb - 1) / tb;
    int gSp = ((n * 32) + tb - 1) / tb;
    int gGemm = (n + TROWS - 1) / TROWS;
    int B = (n + SCAN_CHUNK - 1) / SCAN_CHUNK;
    int nf4 = n * 32;
    int gConv = (nf4 + tb - 1) / tb;

    // fork 1: feature conversion (independent) overlaps setup/count/norm
    cudaEventRecord(evStart, 0);
    cudaStreamWaitEvent(s2, evStart, 0);
    fconv_kernel<<<gConv, tb, 0, s2>>>(features, F16, nf4);

    setup_kernel<<<gN, tb>>>(W1, W2, n);
    count_deg_kernel<<<gE2, tb>>>(src, dst, E2, E, n);
    norm_kernel<<<gN, tb>>>(n);
    cudaEventRecord(evNorm, 0);

    // fork 2: gemm1 on s2 (after convert [in-order on s2] + norm) ∥ CSR build on s0
    cudaStreamWaitEvent(s2, evNorm, 0);
    gemm_tc_kernel<1><<<gGemm, 256, GEMM_SMEM, s2>>>(F16, w1t, G, n);
    cudaEventRecord(evConvGemm, s2);

    scan_reduce_kernel<<<B, 256>>>(n);
    scan_partials_kernel<<<1, 128>>>(B, E);
    scan_down_kernel<<<B, 256>>>(n);
    fill_csr_kernel<<<gE2, tb>>>(src, dst, E2, E, n);

    // join
    cudaStreamWaitEvent(0, evConvGemm, 0);

    // layer 1 aggregation (+ nd, bias, relu, layer-2 ns folded) -> h1 (fp16)
    spmm_kernel<__half, 1><<<gSp, tb>>>(G, b1, h1, n);
    // layer 2
    gemm_tc_kernel<0><<<gGemm, 256, GEMM_SMEM>>>(h1, w2t, G, n);
    spmm_kernel<float, 0><<<gSp, tb>>>(G, b2, out, n);
}

// round 16
// speedup vs baseline: 1.0030x; 1.0030x over previous
#include <cuda_runtime.h>
#include <cuda_bf16.h>
#include <cuda_fp16.h>
#include <cstdint>

#define NN 100000
#define EE 1600000
#define DD 128
#define SCAN_CHUNK 1024
#define SCAN_B ((NN + SCAN_CHUNK - 1) / SCAN_CHUNK)   // 98

// ---------------- static device scratch (no allocations allowed) ----------------
__device__ int    g_outdeg[NN];
__device__ int    g_indeg[NN];
__device__ float  g_nsrc[NN];
__device__ float  g_ndst[NN];
__device__ int    g_off[NN + 1];
__device__ int    g_cur[NN];
__device__ int    g_part[SCAN_B + 1];
__device__ int    g_esrc[EE];
__device__ __half g_G[(size_t)NN * DD];    // GEMM output (gather source)
__device__ __half g_h1[(size_t)NN * DD];   // layer-1 activations (ns2-scaled)
__device__ __half g_W1t[DD * DD];          // W1 fp16, transposed [N,K]
__device__ __half g_W2t[DD * DD];          // W2 fp16, transposed [N,K]

__device__ __forceinline__ uint32_t smem_u32(const void* p) {
    uint32_t a;
    asm("{ .reg .u64 t; cvta.to.shared.u64 t, %1; cvt.u32.u64 %0, t; }" : "=r"(a) : "l"(p));
    return a;
}

// ---------------- fused setup: zero degrees + convert/transpose both W ----------------
__global__ __launch_bounds__(256)
void setup_kernel(const float* __restrict__ W1, const float* __restrict__ W2, int n) {
    int i = blockIdx.x * blockDim.x + threadIdx.x;
    if (i < n) { g_outdeg[i] = 0; g_indeg[i] = 0; }
    if (i < DD * DD) {
        int k = i >> 7, nn = i & 127;
        g_W1t[nn * DD + k] = __float2half_rn(W1[i]);
        g_W2t[nn * DD + k] = __float2half_rn(W2[i]);
    }
}

// 2 edges per thread
__global__ __launch_bounds__(256)
void count_deg_kernel(const int* __restrict__ src, const int* __restrict__ dst,
                      int E2, int E, int n) {
    int t = blockIdx.x * blockDim.x + threadIdx.x;
    if (t < E2) {
        int e = t * 2;
        if (e + 1 < E) {
            int2 s = *(const int2*)(src + e);
            int2 d = *(const int2*)(dst + e);
            if ((unsigned)s.x < (unsigned)n) atomicAdd(&g_outdeg[s.x], 1);
            if ((unsigned)s.y < (unsigned)n) atomicAdd(&g_outdeg[s.y], 1);
            if ((unsigned)d.x < (unsigned)n) atomicAdd(&g_indeg[d.x], 1);
            if ((unsigned)d.y < (unsigned)n) atomicAdd(&g_indeg[d.y], 1);
        } else {
            int s = src[e], d = dst[e];
            if ((unsigned)s < (unsigned)n) atomicAdd(&g_outdeg[s], 1);
            if ((unsigned)d < (unsigned)n) atomicAdd(&g_indeg[d], 1);
        }
    }
}

// norms
__global__ __launch_bounds__(256)
void norm_kernel(int n) {
    int i = blockIdx.x * blockDim.x + threadIdx.x;
    if (i < n) {
        g_nsrc[i] = rsqrtf(fmaxf((float)g_outdeg[i], 1.0f));
        g_ndst[i] = rsqrtf(fmaxf((float)g_indeg[i], 1.0f));
    }
}

// ---- scan pass 1 ----
__global__ __launch_bounds__(256)
void scan_reduce_kernel(int n) {
    __shared__ int wsum[8];
    int b = blockIdx.x;
    int tid = threadIdx.x;
    int idx = b * SCAN_CHUNK + tid * 4;
    int s = 0;
    #pragma unroll
    for (int t = 0; t < 4; t++)
        if (idx + t < n) s += g_indeg[idx + t];
    #pragma unroll
    for (int o = 16; o > 0; o >>= 1) s += __shfl_down_sync(0xffffffffu, s, o);
    int lane = tid & 31, wid = tid >> 5;
    if (lane == 0) wsum[wid] = s;
    __syncthreads();
    if (tid == 0) {
        int t = 0;
        #pragma unroll
        for (int w = 0; w < 8; w++) t += wsum[w];
        g_part[b] = t;
    }
}

__global__ __launch_bounds__(128)
void scan_partials_kernel(int B, int E) {
    __shared__ int sdata[128];
    int tid = threadIdx.x;
    int v = (tid < B) ? g_part[tid] : 0;
    sdata[tid] = v;
    __syncthreads();
    #pragma unroll
    for (int o = 1; o < 128; o <<= 1) {
        int t = (tid >= o) ? sdata[tid - o] : 0;
        __syncthreads();
        sdata[tid] += t;
        __syncthreads();
    }
    if (tid < B) g_part[tid] = sdata[tid] - v;
    if (tid == 0) g_off[NN] = E;
}

__global__ __launch_bounds__(256)
void scan_down_kernel(int n) {
    __shared__ int wscan[8];
    int b = blockIdx.x;
    int tid = threadIdx.x;
    int lane = tid & 31, wid = tid >> 5;
    int idx = b * SCAN_CHUNK + tid * 4;
    int v0 = 0, v1 = 0, v2 = 0, v3 = 0;
    if (idx + 0 < n) v0 = g_indeg[idx + 0];
    if (idx + 1 < n) v1 = g_indeg[idx + 1];
    if (idx + 2 < n) v2 = g_indeg[idx + 2];
    if (idx + 3 < n) v3 = g_indeg[idx + 3];
    int tsum = v0 + v1 + v2 + v3;
    int x = tsum;
    #pragma unroll
    for (int o = 1; o < 32; o <<= 1) {
        int y = __shfl_up_sync(0xffffffffu, x, o);
        if (lane >= o) x += y;
    }
    if (lane == 31) wscan[wid] = x;
    __syncthreads();
    if (wid == 0 && lane < 8) {
        int s = wscan[lane];
        #pragma unroll
        for (int o = 1; o < 8; o <<= 1) {
            int y = __shfl_up_sync(0x000000ffu, s, o);
            if (lane >= o) s += y;
        }
        wscan[lane] = s;
    }
    __syncthreads();
    int base = g_part[b] + (wid ? wscan[wid - 1] : 0) + (x - tsum);
    if (idx + 0 < n) { g_off[idx + 0] = base;            g_cur[idx + 0] = base; }
    if (idx + 1 < n) { g_off[idx + 1] = base + v0;       g_cur[idx + 1] = base + v0; }
    if (idx + 2 < n) { int t = base + v0 + v1;      g_off[idx + 2] = t; g_cur[idx + 2] = t; }
    if (idx + 3 < n) { int t = base + v0 + v1 + v2; g_off[idx + 3] = t; g_cur[idx + 3] = t; }
}

// 2 edges per thread
__global__ __launch_bounds__(256)
void fill_csr_kernel(const int* __restrict__ src, const int* __restrict__ dst,
                     int E2, int E, int n) {
    int t = blockIdx.x * blockDim.x + threadIdx.x;
    if (t < E2) {
        int e = t * 2;
        if (e + 1 < E) {
            int2 s = *(const int2*)(src + e);
            int2 d = *(const int2*)(dst + e);
            if ((unsigned)s.x < (unsigned)n && (unsigned)d.x < (unsigned)n)
                g_esrc[atomicAdd(&g_cur[d.x], 1)] = s.x;
            if ((unsigned)s.y < (unsigned)n && (unsigned)d.y < (unsigned)n)
                g_esrc[atomicAdd(&g_cur[d.y], 1)] = s.y;
        } else {
            int s = src[e], d = dst[e];
            if ((unsigned)s < (unsigned)n && (unsigned)d < (unsigned)n)
                g_esrc[atomicAdd(&g_cur[d], 1)] = s;
        }
    }
}

// ---------------- pull-based SpMM (fp16 gather) ----------------
// EDGE_NS: per-edge weight nsrc[src] (warp-uniform broadcast load).
// OUT_NS : fold next layer's nsrc into stored activation.
// out[d] = [ns_d ⊙] relu(nd[d] * Σ_e [ns_src ·] G[src_e] + bias)
template <typename TOut, int EDGE_NS, int OUT_NS>
__global__ __launch_bounds__(256)
void spmm_kernel(const __half* __restrict__ G, const float* __restrict__ bias,
                 TOut* __restrict__ out, int n) {
    int gw = (blockIdx.x * blockDim.x + threadIdx.x) >> 5;
    if (gw >= n) return;
    int lane = threadIdx.x & 31;
    int beg = g_off[gw];
    int end = g_off[gw + 1];
    const uint2* hp = (const uint2*)G;
    float4 acc = make_float4(0.f, 0.f, 0.f, 0.f);
    int e = beg;
    for (; e + 3 < end; e += 4) {
        int u0 = g_esrc[e], u1 = g_esrc[e + 1], u2 = g_esrc[e + 2], u3 = g_esrc[e + 3];
        uint2 a = hp[(size_t)u0 * 32 + lane];
        uint2 b = hp[(size_t)u1 * 32 + lane];
        uint2 c = hp[(size_t)u2 * 32 + lane];
        uint2 d = hp[(size_t)u3 * 32 + lane];
        float w0 = 1.f, w1 = 1.f, w2 = 1.f, w3 = 1.f;
        if constexpr (EDGE_NS) {
            w0 = g_nsrc[u0]; w1 = g_nsrc[u1]; w2 = g_nsrc[u2]; w3 = g_nsrc[u3];
        }
        float2 f;
        f = __half22float2(*(__half2*)&a.x); acc.x = fmaf(w0, f.x, acc.x); acc.y = fmaf(w0, f.y, acc.y);
        f = __half22float2(*(__half2*)&a.y); acc.z = fmaf(w0, f.x, acc.z); acc.w = fmaf(w0, f.y, acc.w);
        f = __half22float2(*(__half2*)&b.x); acc.x = fmaf(w1, f.x, acc.x); acc.y = fmaf(w1, f.y, acc.y);
        f = __half22float2(*(__half2*)&b.y); acc.z = fmaf(w1, f.x, acc.z); acc.w = fmaf(w1, f.y, acc.w);
        f = __half22float2(*(__half2*)&c.x); acc.x = fmaf(w2, f.x, acc.x); acc.y = fmaf(w2, f.y, acc.y);
        f = __half22float2(*(__half2*)&c.y); acc.z = fmaf(w2, f.x, acc.z); acc.w = fmaf(w2, f.y, acc.w);
        f = __half22float2(*(__half2*)&d.x); acc.x = fmaf(w3, f.x, acc.x); acc.y = fmaf(w3, f.y, acc.y);
        f = __half22float2(*(__half2*)&d.y); acc.z = fmaf(w3, f.x, acc.z); acc.w = fmaf(w3, f.y, acc.w);
    }
    for (; e < end; e++) {
        int u0 = g_esrc[e];
        uint2 a = hp[(size_t)u0 * 32 + lane];
        float w0 = 1.f;
        if constexpr (EDGE_NS) w0 = g_nsrc[u0];
        float2 f;
        f = __half22float2(*(__half2*)&a.x); acc.x = fmaf(w0, f.x, acc.x); acc.y = fmaf(w0, f.y, acc.y);
        f = __half22float2(*(__half2*)&a.y); acc.z = fmaf(w0, f.x, acc.z); acc.w = fmaf(w0, f.y, acc.w);
    }
    float nd = g_ndst[gw];
    float4 b4 = ((const float4*)bias)[lane];
    float4 o;
    o.x = fmaxf(acc.x * nd + b4.x, 0.f);
    o.y = fmaxf(acc.y * nd + b4.y, 0.f);
    o.z = fmaxf(acc.z * nd + b4.z, 0.f);
    o.w = fmaxf(acc.w * nd + b4.w, 0.f);
    if constexpr (OUT_NS) {
        float ns = g_nsrc[gw];
        o.x *= ns; o.y *= ns; o.z *= ns; o.w *= ns;
    }
    if constexpr (sizeof(TOut) == 4) {
        ((float4*)out)[(size_t)gw * 32 + lane] = o;
    } else {
        uint2 p;
        *(__half2*)&p.x = __floats2half2_rn(o.x, o.y);
        *(__half2*)&p.y = __floats2half2_rn(o.z, o.w);
        ((uint2*)out)[(size_t)gw * 32 + lane] = p;
    }
}

// ---------------- HMMA GEMM: C = A @ W, fp16 out, single-pass fp16 W ----------------
// 2x4 warp tiling: warp = 64 M-rows x 32 N-cols. smem 69.6KB -> 3 CTAs/SM. Coalesced loads.
#define GP 272
#define TROWS 128
#define SM_A   0
#define SM_W   (TROWS * GP)
#define GEMM_SMEM ((TROWS + 128) * GP)   // 69632

__device__ __forceinline__ void ldsm_x4(uint32_t* r, uint32_t addr) {
    asm volatile("ldmatrix.sync.aligned.m8n8.x4.shared.b16 {%0,%1,%2,%3}, [%4];"
                 : "=r"(r[0]), "=r"(r[1]), "=r"(r[2]), "=r"(r[3]) : "r"(addr));
}
__device__ __forceinline__ void mma_f16(float* c, const uint32_t* a, uint32_t b0, uint32_t b1) {
    asm volatile("mma.sync.aligned.m16n8k16.row.col.f32.f16.f16.f32 "
                 "{%0,%1,%2,%3}, {%4,%5,%6,%7}, {%8,%9}, {%0,%1,%2,%3};"
                 : "+f"(c[0]), "+f"(c[1]), "+f"(c[2]), "+f"(c[3])
                 : "r"(a[0]), "r"(a[1]), "r"(a[2]), "r"(a[3]), "r"(b0), "r"(b1));
}

template <int AFP32>
__global__ __launch_bounds__(256, 3)
void gemm_tc_kernel(const void* __restrict__ Av,
                    const __half* __restrict__ W,
                    __half* __restrict__ C, int n) {
    extern __shared__ char sm[];
    uint32_t base = smem_u32(sm);
    const int tid = threadIdx.x;
    const int w = tid >> 5, lane = tid & 31;
    const int wm = w >> 2;           // 0..1 : M-warp  (64 rows)
    const int wn = w & 3;            // 0..3 : N-warp  (32 cols)
    const int row0 = blockIdx.x * TROWS;

    // W tile: 128 rows x 256B (fp16), coalesced
    for (int i = tid; i < 2048; i += 256) {
        int rr = i >> 4, q = i & 15;
        *(uint4*)(sm + SM_W + rr * GP + q * 16) = ((const uint4*)W)[i];
    }
    // A tile (fp16 in smem), fully coalesced loads
    if constexpr (AFP32) {
        const float4* ap = (const float4*)Av;   // 32 f4 per row
        #pragma unroll
        for (int i = 0; i < 16; i++) {
            int f = tid + 256 * i;              // 0..4095
            int r = f >> 5, c4 = f & 31;
            int gr = row0 + r;
            float4 v = make_float4(0.f, 0.f, 0.f, 0.f);
            if (gr < n) v = ap[(size_t)gr * 32 + c4];
            uint2 pk;
            *(__half2*)&pk.x = __floats2half2_rn(v.x, v.y);
            *(__half2*)&pk.y = __floats2half2_rn(v.z, v.w);
            *(uint2*)(sm + SM_A + r * GP + c4 * 8) = pk;
        }
    } else {
        const uint4* ap = (const uint4*)Av;     // 16 u4 per row
        #pragma unroll
        for (int i = 0; i < 8; i++) {
            int f = tid + 256 * i;              // 0..2047
            int r = f >> 4, c8 = f & 15;
            int gr = row0 + r;
            uint4 v = make_uint4(0u, 0u, 0u, 0u);
            if (gr < n) v = ap[(size_t)gr * 16 + c8];
            *(uint4*)(sm + SM_A + r * GP + c8 * 16) = v;
        }
    }
    __syncthreads();

    // acc[ab][np][4]: 4 A-blocks (16 rows) x 4 n8-blocks (8 cols)
    float acc[4][4][4];
    #pragma unroll
    for (int a = 0; a < 4; a++)
        #pragma unroll
        for (int p = 0; p < 4; p++)
            #pragma unroll
            for (int q = 0; q < 4; q++) acc[a][p][q] = 0.f;

    int i4 = lane >> 3, l7 = lane & 7;
    uint32_t aRowIn = (uint32_t)((i4 & 1) * 8 + l7);
    uint32_t aK8    = (uint32_t)((i4 >> 1) * 8);
    uint32_t aBase = base + SM_A + (wm * 64 + aRowIn) * GP + aK8 * 2;
    uint32_t wRowIn = (uint32_t)((lane & 7) + ((lane >> 4) << 3));
    uint32_t wK8    = (uint32_t)(((lane >> 3) & 1) * 8);
    uint32_t wW = base + SM_W + (wn * 32 + wRowIn) * GP + wK8 * 2;

    #pragma unroll
    for (int kk = 0; kk < 8; kk++) {
        uint32_t wh0[4], wh1[4];
        ldsm_x4(wh0, wW + kk * 32);               // j-pair 0: n8 blocks 0,1
        ldsm_x4(wh1, wW + 16 * GP + kk * 32);     // j-pair 1: n8 blocks 2,3
        #pragma unroll
        for (int ab = 0; ab < 4; ab++) {
            uint32_t ah[4];
            ldsm_x4(ah, aBase + ab * 16 * GP + kk * 32);
            mma_f16(acc[ab][0], ah, wh0[0], wh0[1]);
            mma_f16(acc[ab][1], ah, wh0[2], wh0[3]);
            mma_f16(acc[ab][2], ah, wh1[0], wh1[1]);
            mma_f16(acc[ab][3], ah, wh1[2], wh1[3]);
        }
    }

    // epilogue: write fp16
    int c0 = (lane & 3) * 2;
    #pragma unroll
    for (int ab = 0; ab < 4; ab++) {
        int r0 = row0 + wm * 64 + ab * 16 + (lane >> 2);
        #pragma unroll
        for (int np = 0; np < 4; np++) {
            int nn = wn * 32 + np * 8 + c0;
            if (r0 < n)
                *(__half2*)(C + (size_t)r0 * DD + nn) = __floats2half2_rn(acc[ab][np][0], acc[ab][np][1]);
            if (r0 + 8 < n)
                *(__half2*)(C + (size_t)(r0 + 8) * DD + nn) = __floats2half2_rn(acc[ab][np][2], acc[ab][np][3]);
        }
    }
}

// ---------------- launch ----------------
extern "C" void kernel_launch(void* const* d_in, const int* in_sizes, int n_in,
                              void* d_out, int out_size) {
    const float* features = (const float*)d_in[0];
    const int*   src      = (const int*)d_in[1];   // jnp.int64 downgrades to int32 (x64 off)
    const int*   dst      = (const int*)d_in[2];
    const float* W1       = (const float*)d_in[3];
    const float* b1       = (const float*)d_in[4];
    const float* W2       = (const float*)d_in[5];
    const float* b2       = (const float*)d_in[6];
    float*       out      = (float*)d_out;

    int n = in_sizes[0] / DD;   // 100000
    int E = in_sizes[1];        // 1600000

    __half *G, *h1, *w1t, *w2t;
    cudaGetSymbolAddress((void**)&G, g_G);
    cudaGetSymbolAddress((void**)&h1, g_h1);
    cudaGetSymbolAddress((void**)&w1t, g_W1t);
    cudaGetSymbolAddress((void**)&w2t, g_W2t);

    cudaFuncSetAttribute(gemm_tc_kernel<1>,
                         cudaFuncAttributeMaxDynamicSharedMemorySize, GEMM_SMEM);
    cudaFuncSetAttribute(gemm_tc_kernel<0>,
                         cudaFuncAttributeMaxDynamicSharedMemorySize, GEMM_SMEM);

    // side stream + events (host-side objects only)
    cudaStream_t s2;
    cudaEvent_t evSetup, evGemm1;
    cudaStreamCreateWithFlags(&s2, cudaStreamNonBlocking);
    cudaEventCreateWithFlags(&evSetup, cudaEventDisableTiming);
    cudaEventCreateWithFlags(&evGemm1, cudaEventDisableTiming);

    int tb = 256;
    int gN = (n + tb - 1) / tb;
    int E2 = (E + 1) / 2;
    int gE2 = (E2 + tb - 1) / tb;
    int gSp = ((n * 32) + tb - 1) / tb;
    int gGemm = (n + TROWS - 1) / TROWS;
    int B = (n + SCAN_CHUNK - 1) / SCAN_CHUNK;

    setup_kernel<<<gN, tb>>>(W1, W2, n);

    // fork: gemm1 = F @ W1 needs ONLY W1t — fully parallel to the whole CSR chain
    cudaEventRecord(evSetup, 0);
    cudaStreamWaitEvent(s2, evSetup, 0);
    gemm_tc_kernel<1><<<gGemm, 256, GEMM_SMEM, s2>>>(features, w1t, G, n);
    cudaEventRecord(evGemm1, s2);

    count_deg_kernel<<<gE2, tb>>>(src, dst, E2, E, n);
    norm_kernel<<<gN, tb>>>(n);
    scan_reduce_kernel<<<B, 256>>>(n);
    scan_partials_kernel<<<1, 128>>>(B, E);
    scan_down_kernel<<<B, 256>>>(n);
    fill_csr_kernel<<<gE2, tb>>>(src, dst, E2, E, n);

    // join
    cudaStreamWaitEvent(0, evGemm1, 0);

    // layer 1 aggregation: per-edge ns, nd+bias+relu, fold layer-2 ns -> h1 (fp16)
    spmm_kernel<__half, 1, 1><<<gSp, tb>>>(G, b1, h1, n);
    // layer 2
    gemm_tc_kernel<0><<<gGemm, 256, GEMM_SMEM>>>(h1, w2t, G, n);
    spmm_kernel<float, 0, 0><<<gSp, tb>>>(G, b2, out, n);
}

// round 17
// speedup vs baseline: 1.1068x; 1.1035x over previous
#include <cuda_runtime.h>
#include <cuda_bf16.h>
#include <cuda_fp16.h>
#include <cstdint>

#define NN 100000
#define EE 1600000
#define DD 128
#define SCAN_CHUNK 1024
#define SCAN_B ((NN + SCAN_CHUNK - 1) / SCAN_CHUNK)   // 98

// ---------------- static device scratch (no allocations allowed) ----------------
__device__ int    g_outdeg[NN];
__device__ int    g_indeg[NN];
__device__ float  g_nsrc[NN];
__device__ float  g_ndst[NN];
__device__ int    g_off[NN + 1];
__device__ int    g_cur[NN];
__device__ int    g_part[SCAN_B + 1];
__device__ int    g_esrc[EE];
__device__ __half g_G[(size_t)NN * DD];    // GEMM output (gather source)
__device__ __half g_h1[(size_t)NN * DD];   // layer-1 activations (ns2-scaled)
__device__ __half g_W1t[DD * DD];          // W1 fp16, transposed [N,K]
__device__ __half g_W2t[DD * DD];          // W2 fp16, transposed [N,K]

__device__ __forceinline__ uint32_t smem_u32(const void* p) {
    uint32_t a;
    asm("{ .reg .u64 t; cvta.to.shared.u64 t, %1; cvt.u32.u64 %0, t; }" : "=r"(a) : "l"(p));
    return a;
}

#define CP16(dst, src) asm volatile("cp.async.cg.shared.global [%0], [%1], 16;" :: "r"(dst), "l"(src))
#define CP_COMMIT()    asm volatile("cp.async.commit_group;" ::: "memory")
#define CP_WAIT(N)     asm volatile("cp.async.wait_group %0;" :: "n"(N) : "memory")

// ---------------- fused setup: zero degrees + convert/transpose both W ----------------
__global__ __launch_bounds__(256)
void setup_kernel(const float* __restrict__ W1, const float* __restrict__ W2, int n) {
    int i = blockIdx.x * blockDim.x + threadIdx.x;
    if (i < n) { g_outdeg[i] = 0; g_indeg[i] = 0; }
    if (i < DD * DD) {
        int k = i >> 7, nn = i & 127;
        g_W1t[nn * DD + k] = __float2half_rn(W1[i]);
        g_W2t[nn * DD + k] = __float2half_rn(W2[i]);
    }
}

// 2 edges per thread
__global__ __launch_bounds__(256)
void count_deg_kernel(const int* __restrict__ src, const int* __restrict__ dst,
                      int E2, int E, int n) {
    int t = blockIdx.x * blockDim.x + threadIdx.x;
    if (t < E2) {
        int e = t * 2;
        if (e + 1 < E) {
            int2 s = *(const int2*)(src + e);
            int2 d = *(const int2*)(dst + e);
            if ((unsigned)s.x < (unsigned)n) atomicAdd(&g_outdeg[s.x], 1);
            if ((unsigned)s.y < (unsigned)n) atomicAdd(&g_outdeg[s.y], 1);
            if ((unsigned)d.x < (unsigned)n) atomicAdd(&g_indeg[d.x], 1);
            if ((unsigned)d.y < (unsigned)n) atomicAdd(&g_indeg[d.y], 1);
        } else {
            int s = src[e], d = dst[e];
            if ((unsigned)s < (unsigned)n) atomicAdd(&g_outdeg[s], 1);
            if ((unsigned)d < (unsigned)n) atomicAdd(&g_indeg[d], 1);
        }
    }
}

// norms
__global__ __launch_bounds__(256)
void norm_kernel(int n) {
    int i = blockIdx.x * blockDim.x + threadIdx.x;
    if (i < n) {
        g_nsrc[i] = rsqrtf(fmaxf((float)g_outdeg[i], 1.0f));
        g_ndst[i] = rsqrtf(fmaxf((float)g_indeg[i], 1.0f));
    }
}

// ---- scan pass 1 ----
__global__ __launch_bounds__(256)
void scan_reduce_kernel(int n) {
    __shared__ int wsum[8];
    int b = blockIdx.x;
    int tid = threadIdx.x;
    int idx = b * SCAN_CHUNK + tid * 4;
    int s = 0;
    #pragma unroll
    for (int t = 0; t < 4; t++)
        if (idx + t < n) s += g_indeg[idx + t];
    #pragma unroll
    for (int o = 16; o > 0; o >>= 1) s += __shfl_down_sync(0xffffffffu, s, o);
    int lane = tid & 31, wid = tid >> 5;
    if (lane == 0) wsum[wid] = s;
    __syncthreads();
    if (tid == 0) {
        int t = 0;
        #pragma unroll
        for (int w = 0; w < 8; w++) t += wsum[w];
        g_part[b] = t;
    }
}

__global__ __launch_bounds__(128)
void scan_partials_kernel(int B, int E) {
    __shared__ int sdata[128];
    int tid = threadIdx.x;
    int v = (tid < B) ? g_part[tid] : 0;
    sdata[tid] = v;
    __syncthreads();
    #pragma unroll
    for (int o = 1; o < 128; o <<= 1) {
        int t = (tid >= o) ? sdata[tid - o] : 0;
        __syncthreads();
        sdata[tid] += t;
        __syncthreads();
    }
    if (tid < B) g_part[tid] = sdata[tid] - v;
    if (tid == 0) g_off[NN] = E;
}

__global__ __launch_bounds__(256)
void scan_down_kernel(int n) {
    __shared__ int wscan[8];
    int b = blockIdx.x;
    int tid = threadIdx.x;
    int lane = tid & 31, wid = tid >> 5;
    int idx = b * SCAN_CHUNK + tid * 4;
    int v0 = 0, v1 = 0, v2 = 0, v3 = 0;
    if (idx + 0 < n) v0 = g_indeg[idx + 0];
    if (idx + 1 < n) v1 = g_indeg[idx + 1];
    if (idx + 2 < n) v2 = g_indeg[idx + 2];
    if (idx + 3 < n) v3 = g_indeg[idx + 3];
    int tsum = v0 + v1 + v2 + v3;
    int x = tsum;
    #pragma unroll
    for (int o = 1; o < 32; o <<= 1) {
        int y = __shfl_up_sync(0xffffffffu, x, o);
        if (lane >= o) x += y;
    }
    if (lane == 31) wscan[wid] = x;
    __syncthreads();
    if (wid == 0 && lane < 8) {
        int s = wscan[lane];
        #pragma unroll
        for (int o = 1; o < 8; o <<= 1) {
            int y = __shfl_up_sync(0x000000ffu, s, o);
            if (lane >= o) s += y;
        }
        wscan[lane] = s;
    }
    __syncthreads();
    int base = g_part[b] + (wid ? wscan[wid - 1] : 0) + (x - tsum);
    if (idx + 0 < n) { g_off[idx + 0] = base;            g_cur[idx + 0] = base; }
    if (idx + 1 < n) { g_off[idx + 1] = base + v0;       g_cur[idx + 1] = base + v0; }
    if (idx + 2 < n) { int t = base + v0 + v1;      g_off[idx + 2] = t; g_cur[idx + 2] = t; }
    if (idx + 3 < n) { int t = base + v0 + v1 + v2; g_off[idx + 3] = t; g_cur[idx + 3] = t; }
}

// 2 edges per thread
__global__ __launch_bounds__(256)
void fill_csr_kernel(const int* __restrict__ src, const int* __restrict__ dst,
                     int E2, int E, int n) {
    int t = blockIdx.x * blockDim.x + threadIdx.x;
    if (t < E2) {
        int e = t * 2;
        if (e + 1 < E) {
            int2 s = *(const int2*)(src + e);
            int2 d = *(const int2*)(dst + e);
            if ((unsigned)s.x < (unsigned)n && (unsigned)d.x < (unsigned)n)
                g_esrc[atomicAdd(&g_cur[d.x], 1)] = s.x;
            if ((unsigned)s.y < (unsigned)n && (unsigned)d.y < (unsigned)n)
                g_esrc[atomicAdd(&g_cur[d.y], 1)] = s.y;
        } else {
            int s = src[e], d = dst[e];
            if ((unsigned)s < (unsigned)n && (unsigned)d < (unsigned)n)
                g_esrc[atomicAdd(&g_cur[d], 1)] = s;
        }
    }
}

// ---------------- pull-based SpMM (fp16 gather) + fused nd/bias/relu (+optional ns fold) ----------------
template <typename TOut, int NSCALE>
__global__ __launch_bounds__(256)
void spmm_kernel(const __half* __restrict__ G, const float* __restrict__ bias,
                 TOut* __restrict__ out, int n) {
    int gw = (blockIdx.x * blockDim.x + threadIdx.x) >> 5;
    if (gw >= n) return;
    int lane = threadIdx.x & 31;
    int beg = g_off[gw];
    int end = g_off[gw + 1];
    const uint2* hp = (const uint2*)G;
    float4 acc = make_float4(0.f, 0.f, 0.f, 0.f);
    int e = beg;
    for (; e + 3 < end; e += 4) {
        int u0 = g_esrc[e], u1 = g_esrc[e + 1], u2 = g_esrc[e + 2], u3 = g_esrc[e + 3];
        uint2 a = hp[(size_t)u0 * 32 + lane];
        uint2 b = hp[(size_t)u1 * 32 + lane];
        uint2 c = hp[(size_t)u2 * 32 + lane];
        uint2 d = hp[(size_t)u3 * 32 + lane];
        float2 f;
        f = __half22float2(*(__half2*)&a.x); acc.x += f.x; acc.y += f.y;
        f = __half22float2(*(__half2*)&a.y); acc.z += f.x; acc.w += f.y;
        f = __half22float2(*(__half2*)&b.x); acc.x += f.x; acc.y += f.y;
        f = __half22float2(*(__half2*)&b.y); acc.z += f.x; acc.w += f.y;
        f = __half22float2(*(__half2*)&c.x); acc.x += f.x; acc.y += f.y;
        f = __half22float2(*(__half2*)&c.y); acc.z += f.x; acc.w += f.y;
        f = __half22float2(*(__half2*)&d.x); acc.x += f.x; acc.y += f.y;
        f = __half22float2(*(__half2*)&d.y); acc.z += f.x; acc.w += f.y;
    }
    for (; e < end; e++) {
        uint2 a = hp[(size_t)g_esrc[e] * 32 + lane];
        float2 f;
        f = __half22float2(*(__half2*)&a.x); acc.x += f.x; acc.y += f.y;
        f = __half22float2(*(__half2*)&a.y); acc.z += f.x; acc.w += f.y;
    }
    float nd = g_ndst[gw];
    float4 b4 = ((const float4*)bias)[lane];
    float4 o;
    o.x = fmaxf(acc.x * nd + b4.x, 0.f);
    o.y = fmaxf(acc.y * nd + b4.y, 0.f);
    o.z = fmaxf(acc.z * nd + b4.z, 0.f);
    o.w = fmaxf(acc.w * nd + b4.w, 0.f);
    if constexpr (NSCALE) {
        float ns = g_nsrc[gw];   // fold next layer's src-norm into stored activation
        o.x *= ns; o.y *= ns; o.z *= ns; o.w *= ns;
    }
    if constexpr (sizeof(TOut) == 4) {
        ((float4*)out)[(size_t)gw * 32 + lane] = o;
    } else {
        uint2 p;
        *(__half2*)&p.x = __floats2half2_rn(o.x, o.y);
        *(__half2*)&p.y = __floats2half2_rn(o.z, o.w);
        ((uint2*)out)[(size_t)gw * 32 + lane] = p;
    }
}

// ---------------- HMMA GEMM, K-split double-buffered ----------------
// smem: W full-K tile (pitch 272, 34816B) + two A-half buffers (pitch 144, 18432B each) = 71680B
#define GP 272
#define AP 144
#define TROWS 128
#define SM_W   0
#define SM_A0  34816
#define SM_A1  (34816 + 18432)
#define GEMM_SMEM (34816 + 2 * 18432)   // 71680

__device__ __forceinline__ void ldsm_x4(uint32_t* r, uint32_t addr) {
    asm volatile("ldmatrix.sync.aligned.m8n8.x4.shared.b16 {%0,%1,%2,%3}, [%4];"
                 : "=r"(r[0]), "=r"(r[1]), "=r"(r[2]), "=r"(r[3]) : "r"(addr));
}
__device__ __forceinline__ void mma_f16(float* c, const uint32_t* a, uint32_t b0, uint32_t b1) {
    asm volatile("mma.sync.aligned.m16n8k16.row.col.f32.f16.f16.f32 "
                 "{%0,%1,%2,%3}, {%4,%5,%6,%7}, {%8,%9}, {%0,%1,%2,%3};"
                 : "+f"(c[0]), "+f"(c[1]), "+f"(c[2]), "+f"(c[3])
                 : "r"(a[0]), "r"(a[1]), "r"(a[2]), "r"(a[3]), "r"(b0), "r"(b1));
}

// compute one K-half (4 k16 steps) from A buffer at aHalf, W at wBase with k-offset hoff bytes
__device__ __forceinline__ void gemm_compute_half(float acc[4][4][4], uint32_t aHalf,
                                                  uint32_t wBase, int hoff) {
    #pragma unroll
    for (int kk = 0; kk < 4; kk++) {
        uint32_t wh0[4], wh1[4];
        ldsm_x4(wh0, wBase + hoff + kk * 32);
        ldsm_x4(wh1, wBase + 16 * GP + hoff + kk * 32);
        #pragma unroll
        for (int ab = 0; ab < 4; ab++) {
            uint32_t ah[4];
            ldsm_x4(ah, aHalf + ab * 16 * AP + kk * 32);
            mma_f16(acc[ab][0], ah, wh0[0], wh0[1]);
            mma_f16(acc[ab][1], ah, wh0[2], wh0[3]);
            mma_f16(acc[ab][2], ah, wh1[0], wh1[1]);
            mma_f16(acc[ab][3], ah, wh1[2], wh1[3]);
        }
    }
}

// ---- gemm1: fp32 A, register-staged pipeline, ns epilogue ----
__global__ __launch_bounds__(256, 2)
void gemm1_kernel(const float* __restrict__ A, const __half* __restrict__ W,
                  __half* __restrict__ C, int n) {
    extern __shared__ char sm[];
    uint32_t base = smem_u32(sm);
    const int tid = threadIdx.x;
    const int w = tid >> 5, lane = tid & 31;
    const int wm = w >> 2, wn = w & 3;
    const int row0 = blockIdx.x * TROWS;

    // W tile (LDG+STS; hot in L2 after setup)
    for (int i = tid; i < 2048; i += 256) {
        int rr = i >> 4, q = i & 15;
        *(uint4*)(sm + SM_W + rr * GP + q * 16) = ((const uint4*)W)[i];
    }
    const float4* ap = (const float4*)A;
    // A half0: load, convert, STS
    #pragma unroll
    for (int i = 0; i < 8; i++) {
        int f = tid + 256 * i;             // 0..2047
        int r = f >> 4, c4 = f & 15;       // row, col-f4 within half (16 f4 = 64 floats)
        int gr = row0 + r;
        float4 v = make_float4(0.f, 0.f, 0.f, 0.f);
        if (gr < n) v = ap[(size_t)gr * 32 + c4];
        uint2 pk;
        *(__half2*)&pk.x = __floats2half2_rn(v.x, v.y);
        *(__half2*)&pk.y = __floats2half2_rn(v.z, v.w);
        *(uint2*)(sm + SM_A0 + r * AP + c4 * 8) = pk;
    }
    __syncthreads();

    // stage half1 loads in registers (held across compute h0)
    float4 stg[8];
    #pragma unroll
    for (int i = 0; i < 8; i++) {
        int f = tid + 256 * i;
        int r = f >> 4, c4 = f & 15;
        int gr = row0 + r;
        stg[i] = (gr < n) ? ap[(size_t)gr * 32 + 16 + c4] : make_float4(0.f, 0.f, 0.f, 0.f);
    }

    float acc[4][4][4];
    #pragma unroll
    for (int a = 0; a < 4; a++)
        #pragma unroll
        for (int p = 0; p < 4; p++)
            #pragma unroll
            for (int q = 0; q < 4; q++) acc[a][p][q] = 0.f;

    int i4 = lane >> 3, l7 = lane & 7;
    uint32_t aRowIn = (uint32_t)((i4 & 1) * 8 + l7);
    uint32_t aK8    = (uint32_t)((i4 >> 1) * 8);
    uint32_t a0 = base + SM_A0 + (wm * 64 + aRowIn) * AP + aK8 * 2;
    uint32_t a1 = base + SM_A1 + (wm * 64 + aRowIn) * AP + aK8 * 2;
    uint32_t wRowIn = (uint32_t)((lane & 7) + ((lane >> 4) << 3));
    uint32_t wK8    = (uint32_t)(((lane >> 3) & 1) * 8);
    uint32_t wBase = base + SM_W + (wn * 32 + wRowIn) * GP + wK8 * 2;

    gemm_compute_half(acc, a0, wBase, 0);

    // convert + STS half1 (loads have landed during compute)
    #pragma unroll
    for (int i = 0; i < 8; i++) {
        int f = tid + 256 * i;
        int r = f >> 4, c4 = f & 15;
        uint2 pk;
        *(__half2*)&pk.x = __floats2half2_rn(stg[i].x, stg[i].y);
        *(__half2*)&pk.y = __floats2half2_rn(stg[i].z, stg[i].w);
        *(uint2*)(sm + SM_A1 + r * AP + c4 * 8) = pk;
    }
    __syncthreads();

    gemm_compute_half(acc, a1, wBase, 128);   // k-offset 64 elems = 128 bytes

    // epilogue: ns row-scale, write fp16
    int c0 = (lane & 3) * 2;
    #pragma unroll
    for (int ab = 0; ab < 4; ab++) {
        int r0 = row0 + wm * 64 + ab * 16 + (lane >> 2);
        float ns0 = (r0 < n) ? g_nsrc[r0] : 0.f;
        float ns1 = (r0 + 8 < n) ? g_nsrc[r0 + 8] : 0.f;
        #pragma unroll
        for (int np = 0; np < 4; np++) {
            int nn = wn * 32 + np * 8 + c0;
            if (r0 < n)
                *(__half2*)(C + (size_t)r0 * DD + nn) = __floats2half2_rn(acc[ab][np][0] * ns0, acc[ab][np][1] * ns0);
            if (r0 + 8 < n)
                *(__half2*)(C + (size_t)(r0 + 8) * DD + nn) = __floats2half2_rn(acc[ab][np][2] * ns1, acc[ab][np][3] * ns1);
        }
    }
}

// ---- gemm2: fp16 A, cp.async double-buffered, no ns ----
__global__ __launch_bounds__(256, 3)
void gemm2_kernel(const __half* __restrict__ A, const __half* __restrict__ W,
                  __half* __restrict__ C, int n) {
    extern __shared__ char sm[];
    uint32_t base = smem_u32(sm);
    const int tid = threadIdx.x;
    const int w = tid >> 5, lane = tid & 31;
    const int wm = w >> 2, wn = w & 3;
    const int row0 = blockIdx.x * TROWS;
    const uint4* au4 = (const uint4*)A;   // 16 u4 per row
    const uint4 zero4 = make_uint4(0u, 0u, 0u, 0u);

    // group 0: A half0 (4 u4/thread; half row = 8 u4)
    #pragma unroll
    for (int i = 0; i < 4; i++) {
        int f = tid + 256 * i;             // 0..1023
        int r = f >> 3, c8 = f & 7;
        int gr = row0 + r;
        uint32_t dst = base + SM_A0 + r * AP + c8 * 16;
        if (gr < n) CP16(dst, au4 + (size_t)gr * 16 + c8);
        else        *(uint4*)(sm + SM_A0 + r * AP + c8 * 16) = zero4;
    }
    CP_COMMIT();
    // group 1: W (8 u4/thread)
    #pragma unroll
    for (int i = 0; i < 8; i++) {
        int idx = tid + 256 * i;
        int rr = idx >> 4, q = idx & 15;
        CP16(base + SM_W + rr * GP + q * 16, ((const uint4*)W) + idx);
    }
    CP_COMMIT();
    // group 2: A half1
    #pragma unroll
    for (int i = 0; i < 4; i++) {
        int f = tid + 256 * i;
        int r = f >> 3, c8 = f & 7;
        int gr = row0 + r;
        uint32_t dst = base + SM_A1 + r * AP + c8 * 16;
        if (gr < n) CP16(dst, au4 + (size_t)gr * 16 + 8 + c8);
        else        *(uint4*)(sm + SM_A1 + r * AP + c8 * 16) = zero4;
    }
    CP_COMMIT();

    float acc[4][4][4];
    #pragma unroll
    for (int a = 0; a < 4; a++)
        #pragma unroll
        for (int p = 0; p < 4; p++)
            #pragma unroll
            for (int q = 0; q < 4; q++) acc[a][p][q] = 0.f;

    int i4 = lane >> 3, l7 = lane & 7;
    uint32_t aRowIn = (uint32_t)((i4 & 1) * 8 + l7);
    uint32_t aK8    = (uint32_t)((i4 >> 1) * 8);
    uint32_t a0 = base + SM_A0 + (wm * 64 + aRowIn) * AP + aK8 * 2;
    uint32_t a1 = base + SM_A1 + (wm * 64 + aRowIn) * AP + aK8 * 2;
    uint32_t wRowIn = (uint32_t)((lane & 7) + ((lane >> 4) << 3));
    uint32_t wK8    = (uint32_t)(((lane >> 3) & 1) * 8);
    uint32_t wBase = base + SM_W + (wn * 32 + wRowIn) * GP + wK8 * 2;

    CP_WAIT(1);            // A half0 + W landed; half1 may still be in flight
    __syncthreads();
    gemm_compute_half(acc, a0, wBase, 0);

    CP_WAIT(0);
    __syncthreads();
    gemm_compute_half(acc, a1, wBase, 128);

    int c0 = (lane & 3) * 2;
    #pragma unroll
    for (int ab = 0; ab < 4; ab++) {
        int r0 = row0 + wm * 64 + ab * 16 + (lane >> 2);
        #pragma unroll
        for (int np = 0; np < 4; np++) {
            int nn = wn * 32 + np * 8 + c0;
            if (r0 < n)
                *(__half2*)(C + (size_t)r0 * DD + nn) = __floats2half2_rn(acc[ab][np][0], acc[ab][np][1]);
            if (r0 + 8 < n)
                *(__half2*)(C + (size_t)(r0 + 8) * DD + nn) = __floats2half2_rn(acc[ab][np][2], acc[ab][np][3]);
        }
    }
}

// ---------------- launch ----------------
extern "C" void kernel_launch(void* const* d_in, const int* in_sizes, int n_in,
                              void* d_out, int out_size) {
    const float* features = (const float*)d_in[0];
    const int*   src      = (const int*)d_in[1];   // jnp.int64 downgrades to int32 (x64 off)
    const int*   dst      = (const int*)d_in[2];
    const float* W1       = (const float*)d_in[3];
    const float* b1       = (const float*)d_in[4];
    const float* W2       = (const float*)d_in[5];
    const float* b2       = (const float*)d_in[6];
    float*       out      = (float*)d_out;

    int n = in_sizes[0] / DD;   // 100000
    int E = in_sizes[1];        // 1600000

    __half *G, *h1, *w1t, *w2t;
    cudaGetSymbolAddress((void**)&G, g_G);
    cudaGetSymbolAddress((void**)&h1, g_h1);
    cudaGetSymbolAddress((void**)&w1t, g_W1t);
    cudaGetSymbolAddress((void**)&w2t, g_W2t);

    cudaFuncSetAttribute(gemm1_kernel, cudaFuncAttributeMaxDynamicSharedMemorySize, GEMM_SMEM);
    cudaFuncSetAttribute(gemm2_kernel, cudaFuncAttributeMaxDynamicSharedMemorySize, GEMM_SMEM);

    int tb = 256;
    int gN = (n + tb - 1) / tb;
    int E2 = (E + 1) / 2;
    int gE2 = (E2 + tb - 1) / tb;
    int gSp = ((n * 32) + tb - 1) / tb;
    int gGemm = (n + TROWS - 1) / TROWS;
    int B = (n + SCAN_CHUNK - 1) / SCAN_CHUNK;

    setup_kernel<<<gN, tb>>>(W1, W2, n);
    count_deg_kernel<<<gE2, tb>>>(src, dst, E2, E, n);
    norm_kernel<<<gN, tb>>>(n);
    gemm1_kernel<<<gGemm, 256, GEMM_SMEM>>>(features, w1t, G, n);
    scan_reduce_kernel<<<B, 256>>>(n);
    scan_partials_kernel<<<1, 128>>>(B, E);
    scan_down_kernel<<<B, 256>>>(n);
    fill_csr_kernel<<<gE2, tb>>>(src, dst, E2, E, n);

    // layer 1 aggregation (+ nd, bias, relu, layer-2 ns folded) -> h1 (fp16)
    spmm_kernel<__half, 1><<<gSp, tb>>>(G, b1, h1, n);
    // layer 2
    gemm2_kernel<<<gGemm, 256, GEMM_SMEM>>>(h1, w2t, G, n);
    spmm_kernel<float, 0><<<gSp, tb>>>(G, b2, out, n);
}